// round 16
// baseline (speedup 1.0000x reference)
#include <cuda_runtime.h>
#include <math.h>

#define NN 50000
#define EE 800000
#define DD 128

// ---------------- scratch (static __device__, no allocs) ----------------
__device__ float g_z[NN * DD];      // h @ W_func^T
__device__ float g_hs[NN * DD];     // h @ W_self^T
__device__ float g_ssrc[NN];        // z . wa[0:128]   (atomic-accumulated)
__device__ float g_sdst[NN];        // z . wa[128:256] (atomic-accumulated)
__device__ float g_se[EE];          // edge_w . wa[256:384]
__device__ int   g_deg[NN];
__device__ int   g_incl[NN];
__device__ int   g_bsum[64];
__device__ int   g_bbase[64];
__device__ int   g_cursor[NN];
__device__ int   g_off[NN + 1];
__device__ unsigned long long g_pair[EE];   // (src<<32 | edge_id) sorted by dst

// ---------------- helpers ----------------
__device__ __forceinline__ unsigned f2tf(float x) {
    unsigned r;
    asm("cvt.rna.tf32.f32 %0, %1;" : "=r"(r) : "f"(x));
    return r;
}

__device__ __forceinline__ void mma_tf32(float* c, unsigned a0, unsigned a1,
                                         unsigned a2, unsigned a3,
                                         unsigned b0, unsigned b1) {
    asm volatile(
        "mma.sync.aligned.m16n8k8.row.col.f32.tf32.tf32.f32 "
        "{%0,%1,%2,%3},{%4,%5,%6,%7},{%8,%9},{%0,%1,%2,%3};\n"
        : "+f"(c[0]), "+f"(c[1]), "+f"(c[2]), "+f"(c[3])
        : "r"(a0), "r"(a1), "r"(a2), "r"(a3), "r"(b0), "r"(b1));
}

__device__ __forceinline__ float warp_sum(float v) {
    #pragma unroll
    for (int o = 16; o; o >>= 1) v += __shfl_xor_sync(0xFFFFFFFFu, v, o);
    return v;
}

// ---------------- degree histogram ----------------
__global__ void k_deg(const int* __restrict__ dst, int E) {
    int e = blockIdx.x * blockDim.x + threadIdx.x;
    if (e < E) atomicAdd(&g_deg[dst[e]], 1);
}

// ---------------- multi-block scan ----------------
__global__ void k_scan1(int N) {
    __shared__ int s[1024];
    int i = blockIdx.x * 1024 + threadIdx.x;
    int v = (i < N) ? g_deg[i] : 0;
    s[threadIdx.x] = v;
    #pragma unroll
    for (int off = 1; off < 1024; off <<= 1) {
        __syncthreads();
        int t = (threadIdx.x >= off) ? s[threadIdx.x - off] : 0;
        __syncthreads();
        s[threadIdx.x] += t;
    }
    if (i < N) g_incl[i] = s[threadIdx.x];
    if (threadIdx.x == 1023) g_bsum[blockIdx.x] = s[1023];
}

__global__ void k_scan2(int nb) {
    if (threadIdx.x == 0) {
        int base = 0;
        for (int b = 0; b < nb; b++) { g_bbase[b] = base; base += g_bsum[b]; }
    }
}

__global__ void k_scan3(int N) {
    int i = blockIdx.x * blockDim.x + threadIdx.x;
    if (i >= N) return;
    int start = g_incl[i] - g_deg[i] + g_bbase[i >> 10];
    g_off[i] = start;
    g_cursor[i] = start;
    if (i == N - 1) g_off[N] = start + g_deg[i];
}

// ---------------- counting-sort scatter: (src, edge_id) by dst ----------------
__global__ void k_scatter0(const int* __restrict__ dst,
                           const int* __restrict__ src, int E) {
    int e = blockIdx.x * blockDim.x + threadIdx.x;
    if (e >= E) return;
    int d = dst[e];
    int p = atomicAdd(&g_cursor[d], 1);
    g_pair[p] = ((unsigned long long)(unsigned)src[e] << 32) | (unsigned)e;
}

// ---------------- dual tf32 GEMM: 64-row tiles, 256 thr, 2 CTAs/SM ----------------
__global__ __launch_bounds__(256, 2) void k_gemm_dual(
    const float* __restrict__ h, const float* __restrict__ Ws,
    const float* __restrict__ Wf, const float* __restrict__ Watt, int N) {
    extern __shared__ unsigned smem[];
    unsigned* sHp = smem;                 // 64 x 136 paired tf32 of A tile
    unsigned* sW  = smem + 64 * 136;      // 128 x 136 paired tf32 of W

    int tid = threadIdx.x;
    int lane = tid & 31, wid = tid >> 5;
    int tg = lane & 3, gid = lane >> 2;
    int wm = wid & 3;                     // 4 m-slots x 16 rows
    int wn = wid >> 2;                    // 2 n-slots x 64 cols
    int row0 = blockIdx.x * 64;

    // stage A tile paired: sHp[r*136 + kt*8 + tg2*2 + hi] = tf32(A[r][kt*8+tg2+4*hi])
    for (int i = tid; i < 64 * 128; i += 256) {
        int r = i >> 7, c = i & 127;
        int kt = c >> 3, within = c & 7;
        int tg2 = within & 3, hi = within >> 2;
        float v = (row0 + r < N) ? h[(size_t)(row0 + r) * 128 + c] : 0.f;
        sHp[r * 136 + kt * 8 + tg2 * 2 + hi] = f2tf(v);
    }

    const float* Wm2[2] = {Ws, Wf};
    float* Om[2] = {g_hs, g_z};

    int r1 = row0 + wm * 16 + gid;
    int r2 = r1 + 8;
    int aoff1 = (wm * 16 + gid) * 136;
    int aoff2 = aoff1 + 8 * 136;

    for (int m = 0; m < 2; m++) {
        __syncthreads();
        const float* W = Wm2[m];
        for (int i = tid; i < 128 * 128; i += 256) {
            int r = i >> 7, c = i & 127;
            int kt = c >> 3, within = c & 7;
            int tg2 = within & 3, hi = within >> 2;
            sW[r * 136 + kt * 8 + tg2 * 2 + hi] = f2tf(W[i]);
        }
        __syncthreads();

        float acc[8][4];
        #pragma unroll
        for (int nt = 0; nt < 8; nt++)
            #pragma unroll
            for (int q = 0; q < 4; q++) acc[nt][q] = 0.f;

        #pragma unroll
        for (int kt = 0; kt < 16; kt++) {
            int ko = kt * 8 + tg * 2;
            uint2 aA = *(const uint2*)&sHp[aoff1 + ko];
            uint2 aB = *(const uint2*)&sHp[aoff2 + ko];
            #pragma unroll
            for (int nt = 0; nt < 8; nt++) {
                uint2 b = *(const uint2*)&sW[(wn * 64 + nt * 8 + gid) * 136 + ko];
                mma_tf32(acc[nt], aA.x, aB.x, aA.y, aB.y, b.x, b.y);
            }
        }

        float* O = Om[m];
        #pragma unroll
        for (int nt = 0; nt < 8; nt++) {
            int col = wn * 64 + nt * 8 + tg * 2;
            if (r1 < N) *(float2*)&O[(size_t)r1 * 128 + col] = make_float2(acc[nt][0], acc[nt][1]);
            if (r2 < N) *(float2*)&O[(size_t)r2 * 128 + col] = make_float2(acc[nt][2], acc[nt][3]);
        }

        if (m == 1) {
            float p1a = 0.f, p1b = 0.f, p2a = 0.f, p2b = 0.f;
            #pragma unroll
            for (int nt = 0; nt < 8; nt++) {
                int c0 = wn * 64 + nt * 8 + tg * 2;
                float wa0 = Watt[c0],        wa1 = Watt[c0 + 1];
                float wb0 = Watt[128 + c0],  wb1 = Watt[128 + c0 + 1];
                p1a += acc[nt][0] * wa0 + acc[nt][1] * wa1;
                p1b += acc[nt][0] * wb0 + acc[nt][1] * wb1;
                p2a += acc[nt][2] * wa0 + acc[nt][3] * wa1;
                p2b += acc[nt][2] * wb0 + acc[nt][3] * wb1;
            }
            #pragma unroll
            for (int o = 1; o < 4; o <<= 1) {
                p1a += __shfl_xor_sync(0xFFFFFFFFu, p1a, o);
                p1b += __shfl_xor_sync(0xFFFFFFFFu, p1b, o);
                p2a += __shfl_xor_sync(0xFFFFFFFFu, p2a, o);
                p2b += __shfl_xor_sync(0xFFFFFFFFu, p2b, o);
            }
            if (tg == 0) {
                if (r1 < N) { atomicAdd(&g_ssrc[r1], p1a); atomicAdd(&g_sdst[r1], p1b); }
                if (r2 < N) { atomicAdd(&g_ssrc[r2], p2a); atomicAdd(&g_sdst[r2], p2b); }
            }
        }
    }
}

// ---------------- edge pre-dot: s_e = edge_w . wa[256:384]  (16 edges/warp) ----------------
__global__ __launch_bounds__(256) void k_edge_se(const float* __restrict__ ew,
                                                 const float* __restrict__ Watt, int E) {
    int wid = (blockIdx.x * blockDim.x + threadIdx.x) >> 5;
    int lane = threadIdx.x & 31;
    int base = wid * 16;
    if (base >= E) return;

    float4 w4 = ((const float4*)Watt)[64 + lane];

    float s[16];
    #pragma unroll
    for (int j = 0; j < 16; j++) {
        float4 e4 = make_float4(0.f, 0.f, 0.f, 0.f);
        if (base + j < E) e4 = ((const float4*)ew)[(size_t)(base + j) * 32 + lane];
        s[j] = e4.x * w4.x + e4.y * w4.y + e4.z * w4.z + e4.w * w4.w;
    }

    #pragma unroll
    for (int o = 16; o; o >>= 1) {
        #pragma unroll
        for (int j = 0; j < 16; j++)
            s[j] += __shfl_xor_sync(0xFFFFFFFFu, s[j], o);
    }

    if (lane < 16) {
        int e = base + lane;
        if (e < E) {
            float se = s[0];
            #pragma unroll
            for (int j = 1; j < 16; j++)
                if (lane == j) se = s[j];
            g_se[e] = se;
        }
    }
}

// ---------------- per-dst: inline logit + softmax (no max-sub) + gather ----------------
__global__ __launch_bounds__(256, 3) void k_aggregate(const float* __restrict__ h,
                                                      float* __restrict__ out, int N) {
    __shared__ float swl[8][32];
    __shared__ int   ssv[8][32];
    int w = threadIdx.x >> 5;
    int lane = threadIdx.x & 31;
    int wid = (blockIdx.x * blockDim.x + threadIdx.x) >> 5;
    if (wid >= N) return;

    int beg = g_off[wid], end = g_off[wid + 1];
    int deg = end - beg;
    float4 hv = ((const float4*)h)[(size_t)wid * 32 + lane];
    float4 res;

    if (deg == 0) {
        res.x = hv.x + fmaxf(hv.x, 0.f);
        res.y = hv.y + fmaxf(hv.y, 0.f);
        res.z = hv.z + fmaxf(hv.z, 0.f);
        res.w = hv.w + fmaxf(hv.w, 0.f);
    } else {
        float sdst_w = g_sdst[wid];
        float4 acc = make_float4(0.f, 0.f, 0.f, 0.f);
        float denom = 0.f;

        if (deg <= 32) {
            // fast path: no max subtraction (logits bounded; factor cancels)
            float wl = 0.f;
            int sv = 0;
            if (lane < deg) {
                unsigned long long u = g_pair[beg + lane];
                sv = (int)(u >> 32);
                int e = (int)(unsigned)u;
                float l = g_ssrc[sv] + sdst_w + g_se[e];
                l = l > 0.f ? l : 0.01f * l;
                wl = __expf(l);
            }
            denom = wl;
            swl[w][lane] = wl;
            ssv[w][lane] = sv;
            __syncwarp();

            int k = 0;
            for (; k + 8 <= deg; k += 8) {
                float4 zb[8];
                #pragma unroll
                for (int j = 0; j < 8; j++) {
                    int aj = ssv[w][k + j];
                    zb[j] = ((const float4*)g_z)[(size_t)aj * 32 + lane];
                }
                #pragma unroll
                for (int j = 0; j < 8; j++) {
                    float wk = swl[w][k + j];
                    acc.x += wk * zb[j].x;
                    acc.y += wk * zb[j].y;
                    acc.z += wk * zb[j].z;
                    acc.w += wk * zb[j].w;
                }
            }
            for (; k < deg; k++) {
                float wk = swl[w][k];
                int   ak = ssv[w][k];
                float4 z0 = ((const float4*)g_z)[(size_t)ak * 32 + lane];
                acc.x += wk * z0.x;
                acc.y += wk * z0.y;
                acc.z += wk * z0.z;
                acc.w += wk * z0.w;
            }
        } else {
            // rare path (deg > 32), also without max subtraction
            for (int i = beg; i < end; i += 32) {
                int cnt = end - i; if (cnt > 32) cnt = 32;
                float wl = 0.f;
                int sv = 0;
                if (lane < cnt) {
                    unsigned long long u = g_pair[i + lane];
                    sv = (int)(u >> 32);
                    float l = g_ssrc[sv] + sdst_w + g_se[(int)(unsigned)u];
                    l = l > 0.f ? l : 0.01f * l;
                    wl = __expf(l);
                }
                denom += wl;
                swl[w][lane] = wl;
                ssv[w][lane] = sv;
                __syncwarp();
                for (int k = 0; k < cnt; k++) {
                    float wk = swl[w][k];
                    int   ak = ssv[w][k];
                    float4 z0 = ((const float4*)g_z)[(size_t)ak * 32 + lane];
                    acc.x += wk * z0.x;
                    acc.y += wk * z0.y;
                    acc.z += wk * z0.z;
                    acc.w += wk * z0.w;
                }
                __syncwarp();
            }
        }

        denom = warp_sum(denom);
        float inv = 1.f / fmaxf(denom, 1e-9f);
        float4 hs = ((const float4*)g_hs)[(size_t)wid * 32 + lane];
        float tx = hs.x + acc.x * inv;
        float ty = hs.y + acc.y * inv;
        float tz = hs.z + acc.z * inv;
        float tw = hs.w + acc.w * inv;
        res.x = hv.x + fmaxf(tx, 0.f);
        res.y = hv.y + fmaxf(ty, 0.f);
        res.z = hv.z + fmaxf(tz, 0.f);
        res.w = hv.w + fmaxf(tw, 0.f);
    }
    ((float4*)out)[(size_t)wid * 32 + lane] = res;
}

// ---------------- launch (fork/join; kernel #4 = gemm for ncu) ----------------
extern "C" void kernel_launch(void* const* d_in, const int* in_sizes, int n_in,
                              void* d_out, int out_size) {
    const float* h    = (const float*)d_in[0];
    const float* ew   = (const float*)d_in[1];
    const float* Ws   = (const float*)d_in[2];
    const float* Wf   = (const float*)d_in[3];
    const float* Watt = (const float*)d_in[4];
    const int*   src  = (const int*)d_in[5];
    const int*   dst  = (const int*)d_in[6];
    float* out = (float*)d_out;

    int N = in_sizes[0] / DD;
    int E = in_sizes[5];

    const size_t gemm_smem = (size_t)(64 * 136 + 128 * 136) * 4;   // ~104.4 KB

    static cudaStream_t sA = nullptr, sB = nullptr;
    static cudaEvent_t evFork = nullptr, evA = nullptr, evB = nullptr;
    if (sA == nullptr) {
        cudaStreamCreateWithFlags(&sA, cudaStreamNonBlocking);
        cudaStreamCreateWithFlags(&sB, cudaStreamNonBlocking);
        cudaEventCreateWithFlags(&evFork, cudaEventDisableTiming);
        cudaEventCreateWithFlags(&evA, cudaEventDisableTiming);
        cudaEventCreateWithFlags(&evB, cudaEventDisableTiming);
        cudaFuncSetAttribute(k_gemm_dual,
                             cudaFuncAttributeMaxDynamicSharedMemorySize,
                             (int)gemm_smem);
    }

    // zero accumulators + degree BEFORE fork
    void *degp = nullptr, *ssrcp = nullptr, *sdstp = nullptr;
    cudaGetSymbolAddress(&degp, g_deg);
    cudaGetSymbolAddress(&ssrcp, g_ssrc);
    cudaGetSymbolAddress(&sdstp, g_sdst);
    cudaMemsetAsync(degp, 0, (size_t)N * sizeof(int), 0);
    cudaMemsetAsync(ssrcp, 0, (size_t)N * sizeof(float), 0);
    cudaMemsetAsync(sdstp, 0, (size_t)N * sizeof(float), 0);

    // fork
    cudaEventRecord(evFork, 0);
    cudaStreamWaitEvent(sA, evFork, 0);
    cudaStreamWaitEvent(sB, evFork, 0);

    // #1 (stream A): 410MB edge_w stream
    int ewarps = (E + 15) / 16;
    k_edge_se<<<(ewarps + 7) / 8, 256, 0, sA>>>(ew, Watt, E);
    cudaEventRecord(evA, sA);

    // #2, #3 (main): deg + scan1
    k_deg<<<(E + 255) / 256, 256>>>(dst, E);
    int nb = (N + 1023) / 1024;
    k_scan1<<<nb, 1024>>>(N);

    // #4 (stream B): GEMM with 2 CTAs/SM  <-- ncu profiles this one
    k_gemm_dual<<<(N + 63) / 64, 256, gemm_smem, sB>>>(h, Ws, Wf, Watt, N);
    cudaEventRecord(evB, sB);

    // #5-#7 (main): scan2, scan3, scatter0
    k_scan2<<<1, 32>>>(nb);
    k_scan3<<<(N + 255) / 256, 256>>>(N);
    k_scatter0<<<(E + 255) / 256, 256>>>(dst, src, E);

    // join
    cudaStreamWaitEvent(0, evA, 0);
    cudaStreamWaitEvent(0, evB, 0);

    // #8: single serial tail kernel
    k_aggregate<<<(N + 7) / 8, 256>>>(h, out, N);
}

// round 17
// speedup vs baseline: 1.0013x; 1.0013x over previous
#include <cuda_runtime.h>
#include <math.h>

#define NN 50000
#define EE 800000
#define DD 128

// ---------------- scratch (static __device__, no allocs) ----------------
__device__ float g_z[NN * DD];      // h @ W_func^T   (keep L2-resident!)
__device__ float g_hs[NN * DD];     // h @ W_self^T
__device__ float g_ssrc[NN];        // z . wa[0:128]   (atomic-accumulated)
__device__ float g_sdst[NN];        // z . wa[128:256] (atomic-accumulated)
__device__ float g_se[EE];          // edge_w . wa[256:384]
__device__ int   g_deg[NN];
__device__ int   g_incl[NN];
__device__ int   g_bsum[64];
__device__ int   g_bbase[64];
__device__ int   g_cursor[NN];
__device__ int   g_off[NN + 1];
__device__ unsigned long long g_pair[EE];   // (src<<32 | edge_id) sorted by dst

// ---------------- helpers ----------------
__device__ __forceinline__ unsigned f2tf(float x) {
    unsigned r;
    asm("cvt.rna.tf32.f32 %0, %1;" : "=r"(r) : "f"(x));
    return r;
}

__device__ __forceinline__ void mma_tf32(float* c, unsigned a0, unsigned a1,
                                         unsigned a2, unsigned a3,
                                         unsigned b0, unsigned b1) {
    asm volatile(
        "mma.sync.aligned.m16n8k8.row.col.f32.tf32.tf32.f32 "
        "{%0,%1,%2,%3},{%4,%5,%6,%7},{%8,%9},{%0,%1,%2,%3};\n"
        : "+f"(c[0]), "+f"(c[1]), "+f"(c[2]), "+f"(c[3])
        : "r"(a0), "r"(a1), "r"(a2), "r"(a3), "r"(b0), "r"(b1));
}

__device__ __forceinline__ float warp_sum(float v) {
    #pragma unroll
    for (int o = 16; o; o >>= 1) v += __shfl_xor_sync(0xFFFFFFFFu, v, o);
    return v;
}

// ---------------- degree histogram ----------------
__global__ void k_deg(const int* __restrict__ dst, int E) {
    int e = blockIdx.x * blockDim.x + threadIdx.x;
    if (e < E) atomicAdd(&g_deg[dst[e]], 1);
}

// ---------------- multi-block scan ----------------
__global__ void k_scan1(int N) {
    __shared__ int s[1024];
    int i = blockIdx.x * 1024 + threadIdx.x;
    int v = (i < N) ? g_deg[i] : 0;
    s[threadIdx.x] = v;
    #pragma unroll
    for (int off = 1; off < 1024; off <<= 1) {
        __syncthreads();
        int t = (threadIdx.x >= off) ? s[threadIdx.x - off] : 0;
        __syncthreads();
        s[threadIdx.x] += t;
    }
    if (i < N) g_incl[i] = s[threadIdx.x];
    if (threadIdx.x == 1023) g_bsum[blockIdx.x] = s[1023];
}

__global__ void k_scan2(int nb) {
    if (threadIdx.x == 0) {
        int base = 0;
        for (int b = 0; b < nb; b++) { g_bbase[b] = base; base += g_bsum[b]; }
    }
}

__global__ void k_scan3(int N) {
    int i = blockIdx.x * blockDim.x + threadIdx.x;
    if (i >= N) return;
    int start = g_incl[i] - g_deg[i] + g_bbase[i >> 10];
    g_off[i] = start;
    g_cursor[i] = start;
    if (i == N - 1) g_off[N] = start + g_deg[i];
}

// ---------------- counting-sort scatter: (src, edge_id) by dst ----------------
__global__ void k_scatter0(const int* __restrict__ dst,
                           const int* __restrict__ src, int E) {
    int e = blockIdx.x * blockDim.x + threadIdx.x;
    if (e >= E) return;
    int d = dst[e];
    int p = atomicAdd(&g_cursor[d], 1);
    g_pair[p] = ((unsigned long long)(unsigned)src[e] << 32) | (unsigned)e;
}

// ---------------- dual tf32 GEMM: 128-row tiles, 512 threads (R15 config) ----------------
__global__ __launch_bounds__(512, 1) void k_gemm_dual(
    const float* __restrict__ h, const float* __restrict__ Ws,
    const float* __restrict__ Wf, const float* __restrict__ Watt, int N) {
    extern __shared__ unsigned smem[];
    unsigned* sHp = smem;                 // 128 x 136 paired tf32 of A tile
    unsigned* sW  = smem + 128 * 136;     // 128 x 136 paired tf32 of W

    int tid = threadIdx.x;
    int lane = tid & 31, wid = tid >> 5;
    int tg = lane & 3, gid = lane >> 2;
    int wm = wid & 7;
    int wn = wid >> 3;
    int row0 = blockIdx.x * 128;

    for (int i = tid; i < 128 * 128; i += 512) {
        int r = i >> 7, c = i & 127;
        int kt = c >> 3, within = c & 7;
        int tg2 = within & 3, hi = within >> 2;
        float v = (row0 + r < N) ? __ldcs(&h[(size_t)(row0 + r) * 128 + c]) : 0.f;
        sHp[r * 136 + kt * 8 + tg2 * 2 + hi] = f2tf(v);
    }

    const float* Wm2[2] = {Ws, Wf};
    float* Om[2] = {g_hs, g_z};

    int r1 = row0 + wm * 16 + gid;
    int r2 = r1 + 8;
    int aoff1 = (wm * 16 + gid) * 136;
    int aoff2 = aoff1 + 8 * 136;

    for (int m = 0; m < 2; m++) {
        __syncthreads();
        const float* W = Wm2[m];
        for (int i = tid; i < 128 * 128; i += 512) {
            int r = i >> 7, c = i & 127;
            int kt = c >> 3, within = c & 7;
            int tg2 = within & 3, hi = within >> 2;
            sW[r * 136 + kt * 8 + tg2 * 2 + hi] = f2tf(W[i]);
        }
        __syncthreads();

        float acc[8][4];
        #pragma unroll
        for (int nt = 0; nt < 8; nt++)
            #pragma unroll
            for (int q = 0; q < 4; q++) acc[nt][q] = 0.f;

        #pragma unroll
        for (int kt = 0; kt < 16; kt++) {
            int ko = kt * 8 + tg * 2;
            uint2 aA = *(const uint2*)&sHp[aoff1 + ko];
            uint2 aB = *(const uint2*)&sHp[aoff2 + ko];
            #pragma unroll
            for (int nt = 0; nt < 8; nt++) {
                uint2 b = *(const uint2*)&sW[(wn * 64 + nt * 8 + gid) * 136 + ko];
                mma_tf32(acc[nt], aA.x, aB.x, aA.y, aB.y, b.x, b.y);
            }
        }

        float* O = Om[m];
        #pragma unroll
        for (int nt = 0; nt < 8; nt++) {
            int col = wn * 64 + nt * 8 + tg * 2;
            if (r1 < N) *(float2*)&O[(size_t)r1 * 128 + col] = make_float2(acc[nt][0], acc[nt][1]);
            if (r2 < N) *(float2*)&O[(size_t)r2 * 128 + col] = make_float2(acc[nt][2], acc[nt][3]);
        }

        if (m == 1) {
            float p1a = 0.f, p1b = 0.f, p2a = 0.f, p2b = 0.f;
            #pragma unroll
            for (int nt = 0; nt < 8; nt++) {
                int c0 = wn * 64 + nt * 8 + tg * 2;
                float wa0 = Watt[c0],        wa1 = Watt[c0 + 1];
                float wb0 = Watt[128 + c0],  wb1 = Watt[128 + c0 + 1];
                p1a += acc[nt][0] * wa0 + acc[nt][1] * wa1;
                p1b += acc[nt][0] * wb0 + acc[nt][1] * wb1;
                p2a += acc[nt][2] * wa0 + acc[nt][3] * wa1;
                p2b += acc[nt][2] * wb0 + acc[nt][3] * wb1;
            }
            #pragma unroll
            for (int o = 1; o < 4; o <<= 1) {
                p1a += __shfl_xor_sync(0xFFFFFFFFu, p1a, o);
                p1b += __shfl_xor_sync(0xFFFFFFFFu, p1b, o);
                p2a += __shfl_xor_sync(0xFFFFFFFFu, p2a, o);
                p2b += __shfl_xor_sync(0xFFFFFFFFu, p2b, o);
            }
            if (tg == 0) {
                if (r1 < N) { atomicAdd(&g_ssrc[r1], p1a); atomicAdd(&g_sdst[r1], p1b); }
                if (r2 < N) { atomicAdd(&g_ssrc[r2], p2a); atomicAdd(&g_sdst[r2], p2b); }
            }
        }
    }
}

// ---------------- edge pre-dot (16 edges/warp), STREAMING loads (keep L2 for z) ----------------
__global__ __launch_bounds__(256) void k_edge_se(const float* __restrict__ ew,
                                                 const float* __restrict__ Watt, int E) {
    int wid = (blockIdx.x * blockDim.x + threadIdx.x) >> 5;
    int lane = threadIdx.x & 31;
    int base = wid * 16;
    if (base >= E) return;

    float4 w4 = ((const float4*)Watt)[64 + lane];

    float s[16];
    #pragma unroll
    for (int j = 0; j < 16; j++) {
        float4 e4 = make_float4(0.f, 0.f, 0.f, 0.f);
        if (base + j < E)
            e4 = __ldcs(&((const float4*)ew)[(size_t)(base + j) * 32 + lane]);
        s[j] = e4.x * w4.x + e4.y * w4.y + e4.z * w4.z + e4.w * w4.w;
    }

    #pragma unroll
    for (int o = 16; o; o >>= 1) {
        #pragma unroll
        for (int j = 0; j < 16; j++)
            s[j] += __shfl_xor_sync(0xFFFFFFFFu, s[j], o);
    }

    if (lane < 16) {
        int e = base + lane;
        if (e < E) {
            float se = s[0];
            #pragma unroll
            for (int j = 1; j < 16; j++)
                if (lane == j) se = s[j];
            g_se[e] = se;
        }
    }
}

// ---------------- per-dst: inline logit + softmax (no max-sub) + gather ----------------
__global__ __launch_bounds__(256, 3) void k_aggregate(const float* __restrict__ h,
                                                      float* __restrict__ out, int N) {
    __shared__ float swl[8][32];
    __shared__ int   ssv[8][32];
    int w = threadIdx.x >> 5;
    int lane = threadIdx.x & 31;
    int wid = (blockIdx.x * blockDim.x + threadIdx.x) >> 5;
    if (wid >= N) return;

    int beg = g_off[wid], end = g_off[wid + 1];
    int deg = end - beg;
    float4 hv = __ldcs(&((const float4*)h)[(size_t)wid * 32 + lane]);  // read-once
    float4 res;

    if (deg == 0) {
        res.x = hv.x + fmaxf(hv.x, 0.f);
        res.y = hv.y + fmaxf(hv.y, 0.f);
        res.z = hv.z + fmaxf(hv.z, 0.f);
        res.w = hv.w + fmaxf(hv.w, 0.f);
    } else {
        float sdst_w = g_sdst[wid];
        float4 acc = make_float4(0.f, 0.f, 0.f, 0.f);
        float denom = 0.f;

        if (deg <= 32) {
            float wl = 0.f;
            int sv = 0;
            if (lane < deg) {
                unsigned long long u = g_pair[beg + lane];
                sv = (int)(u >> 32);
                int e = (int)(unsigned)u;
                float l = g_ssrc[sv] + sdst_w + g_se[e];
                l = l > 0.f ? l : 0.01f * l;
                wl = __expf(l);
            }
            denom = wl;
            swl[w][lane] = wl;
            ssv[w][lane] = sv;
            __syncwarp();

            int k = 0;
            for (; k + 8 <= deg; k += 8) {
                float4 zb[8];
                #pragma unroll
                for (int j = 0; j < 8; j++) {
                    int aj = ssv[w][k + j];
                    zb[j] = ((const float4*)g_z)[(size_t)aj * 32 + lane];
                }
                #pragma unroll
                for (int j = 0; j < 8; j++) {
                    float wk = swl[w][k + j];
                    acc.x += wk * zb[j].x;
                    acc.y += wk * zb[j].y;
                    acc.z += wk * zb[j].z;
                    acc.w += wk * zb[j].w;
                }
            }
            for (; k < deg; k++) {
                float wk = swl[w][k];
                int   ak = ssv[w][k];
                float4 z0 = ((const float4*)g_z)[(size_t)ak * 32 + lane];
                acc.x += wk * z0.x;
                acc.y += wk * z0.y;
                acc.z += wk * z0.z;
                acc.w += wk * z0.w;
            }
        } else {
            for (int i = beg; i < end; i += 32) {
                int cnt = end - i; if (cnt > 32) cnt = 32;
                float wl = 0.f;
                int sv = 0;
                if (lane < cnt) {
                    unsigned long long u = g_pair[i + lane];
                    sv = (int)(u >> 32);
                    float l = g_ssrc[sv] + sdst_w + g_se[(int)(unsigned)u];
                    l = l > 0.f ? l : 0.01f * l;
                    wl = __expf(l);
                }
                denom += wl;
                swl[w][lane] = wl;
                ssv[w][lane] = sv;
                __syncwarp();
                for (int k = 0; k < cnt; k++) {
                    float wk = swl[w][k];
                    int   ak = ssv[w][k];
                    float4 z0 = ((const float4*)g_z)[(size_t)ak * 32 + lane];
                    acc.x += wk * z0.x;
                    acc.y += wk * z0.y;
                    acc.z += wk * z0.z;
                    acc.w += wk * z0.w;
                }
                __syncwarp();
            }
        }

        denom = warp_sum(denom);
        float inv = 1.f / fmaxf(denom, 1e-9f);
        float4 hs = __ldcs(&((const float4*)g_hs)[(size_t)wid * 32 + lane]);  // read-once
        float tx = hs.x + acc.x * inv;
        float ty = hs.y + acc.y * inv;
        float tz = hs.z + acc.z * inv;
        float tw = hs.w + acc.w * inv;
        res.x = hv.x + fmaxf(tx, 0.f);
        res.y = hv.y + fmaxf(ty, 0.f);
        res.z = hv.z + fmaxf(tz, 0.f);
        res.w = hv.w + fmaxf(tw, 0.f);
    }
    __stcs(&((float4*)out)[(size_t)wid * 32 + lane], res);   // write-once, don't pollute L2
}

// ---------------- launch (fork/join) ----------------
extern "C" void kernel_launch(void* const* d_in, const int* in_sizes, int n_in,
                              void* d_out, int out_size) {
    const float* h    = (const float*)d_in[0];
    const float* ew   = (const float*)d_in[1];
    const float* Ws   = (const float*)d_in[2];
    const float* Wf   = (const float*)d_in[3];
    const float* Watt = (const float*)d_in[4];
    const int*   src  = (const int*)d_in[5];
    const int*   dst  = (const int*)d_in[6];
    float* out = (float*)d_out;

    int N = in_sizes[0] / DD;
    int E = in_sizes[5];

    const size_t gemm_smem = (size_t)(128 * 136) * 2 * 4;   // ~139 KB, 1 CTA/SM

    static cudaStream_t sA = nullptr, sB = nullptr;
    static cudaEvent_t evFork = nullptr, evA = nullptr, evB = nullptr;
    if (sA == nullptr) {
        cudaStreamCreateWithFlags(&sA, cudaStreamNonBlocking);
        cudaStreamCreateWithFlags(&sB, cudaStreamNonBlocking);
        cudaEventCreateWithFlags(&evFork, cudaEventDisableTiming);
        cudaEventCreateWithFlags(&evA, cudaEventDisableTiming);
        cudaEventCreateWithFlags(&evB, cudaEventDisableTiming);
        cudaFuncSetAttribute(k_gemm_dual,
                             cudaFuncAttributeMaxDynamicSharedMemorySize,
                             (int)gemm_smem);
    }

    // zero accumulators + degree BEFORE fork
    void *degp = nullptr, *ssrcp = nullptr, *sdstp = nullptr;
    cudaGetSymbolAddress(&degp, g_deg);
    cudaGetSymbolAddress(&ssrcp, g_ssrc);
    cudaGetSymbolAddress(&sdstp, g_sdst);
    cudaMemsetAsync(degp, 0, (size_t)N * sizeof(int), 0);
    cudaMemsetAsync(ssrcp, 0, (size_t)N * sizeof(float), 0);
    cudaMemsetAsync(sdstp, 0, (size_t)N * sizeof(float), 0);

    // fork
    cudaEventRecord(evFork, 0);
    cudaStreamWaitEvent(sA, evFork, 0);
    cudaStreamWaitEvent(sB, evFork, 0);

    // stream A: 410MB edge_w stream (evict-first; leaves L2 to z)
    int ewarps = (E + 15) / 16;
    k_edge_se<<<(ewarps + 7) / 8, 256, 0, sA>>>(ew, Watt, E);
    cudaEventRecord(evA, sA);

    // main: deg + scan1
    k_deg<<<(E + 255) / 256, 256>>>(dst, E);
    int nb = (N + 1023) / 1024;
    k_scan1<<<nb, 1024>>>(N);

    // stream B: GEMM (R15 config)
    k_gemm_dual<<<(N + 127) / 128, 512, gemm_smem, sB>>>(h, Ws, Wf, Watt, N);
    cudaEventRecord(evB, sB);

    // main: scan2, scan3, scatter0
    k_scan2<<<1, 32>>>(nb);
    k_scan3<<<(N + 255) / 256, 256>>>(N);
    k_scatter0<<<(E + 255) / 256, 256>>>(dst, src, E);

    // join
    cudaStreamWaitEvent(0, evA, 0);
    cudaStreamWaitEvent(0, evB, 0);

    // serial tail
    k_aggregate<<<(N + 7) / 8, 256>>>(h, out, N);
}